// round 15
// baseline (speedup 1.0000x reference)
#include <cuda_runtime.h>
#include <cuda_fp16.h>
#include <cstdint>

// Problem constants
#define BATCH  4
#define SEQ    4096
#define M_TOK  (BATCH * SEQ)   // 16384 tokens
#define EDIM   1024
#define HEADS  16
#define DH     64
#define NTOT   3072            // packed N = q|k|v

typedef unsigned long long u64;
typedef unsigned int       u32;

// ---------------------------------------------------------------------------
// Device scratch (alloc-free per harness rules)
// A rows: [Xh(1024) | Xl(1024)]  fp16, residual UNSCALED (denormals OK on TC)
// B rows: [Wh(1024) | Wl(1024)]
// Terms: (hi,hi) + (hi,lo) + (lo,hi), all into one f32 accumulator.
// ---------------------------------------------------------------------------
__device__ __half g_a16[(size_t)M_TOK * 2048];
__device__ __half g_b16[(size_t)NTOT * 2048];
__device__ float  g_bias[NTOT];
__device__ float  g_qkv[(size_t)M_TOK * NTOT];   // q | k | v per row

// ---------------------------------------------------------------------------
// PTX helpers (compute_103-legal: cp.async / ldmatrix / mma.sync)
// ---------------------------------------------------------------------------
__device__ __forceinline__ u32 s2u(const void* p) {
    u32 a;
    asm("{ .reg .u64 t; cvta.to.shared.u64 t, %1; cvt.u32.u64 %0, t; }"
        : "=r"(a) : "l"(p));
    return a;
}
__device__ __forceinline__ void cpa16(u32 dst, const void* src) {
    asm volatile("cp.async.cg.shared.global [%0], [%1], 16;"
                 :: "r"(dst), "l"(src) : "memory");
}
#define CPA_COMMIT() asm volatile("cp.async.commit_group;" ::: "memory")
#define CPA_WAIT1()  asm volatile("cp.async.wait_group 1;" ::: "memory")

__device__ __forceinline__ void ldsm4(u32* r, u32 addr) {
    asm volatile("ldmatrix.sync.aligned.m8n8.x4.shared.b16 {%0,%1,%2,%3}, [%4];"
                 : "=r"(r[0]), "=r"(r[1]), "=r"(r[2]), "=r"(r[3]) : "r"(addr));
}
__device__ __forceinline__ void mma_h32(float* d, const u32* a, const u32* b) {
    asm volatile(
        "mma.sync.aligned.m16n8k16.row.col.f32.f16.f16.f32 "
        "{%0,%1,%2,%3}, {%4,%5,%6,%7}, {%8,%9}, {%0,%1,%2,%3};"
        : "+f"(d[0]), "+f"(d[1]), "+f"(d[2]), "+f"(d[3])
        : "r"(a[0]), "r"(a[1]), "r"(a[2]), "r"(a[3]), "r"(b[0]), "r"(b[1]));
}

// ---------------------------------------------------------------------------
// Fused pack kernel: A split, B split, bias — one launch.
// 16 floats per thread for A/B (4 float4 loads, 4 uint4 stores).
// ---------------------------------------------------------------------------
#define A_BLKS 4096   // (M_TOK*EDIM/16)/256
#define B_BLKS 768    // (3*EDIM*EDIM/16)/256
#define BIAS_BLKS 12

__device__ __forceinline__ void split8(float4 v0, float4 v1, uint4& hi, uint4& lo) {
    float f[8] = {v0.x, v0.y, v0.z, v0.w, v1.x, v1.y, v1.z, v1.w};
    u32 hw[4], lw[4];
    #pragma unroll
    for (int j = 0; j < 4; j++) {
        __half ha = __float2half_rn(f[2 * j]);
        __half hb = __float2half_rn(f[2 * j + 1]);
        __half2 hh = __halves2half2(ha, hb);
        __half2 ll = __halves2half2(
            __float2half_rn(f[2 * j]     - __half2float(ha)),
            __float2half_rn(f[2 * j + 1] - __half2float(hb)));
        hw[j] = *(u32*)&hh;
        lw[j] = *(u32*)&ll;
    }
    hi = make_uint4(hw[0], hw[1], hw[2], hw[3]);
    lo = make_uint4(lw[0], lw[1], lw[2], lw[3]);
}

__device__ __forceinline__ void pack16(const float4* __restrict__ src, int grp,
                                       __half* __restrict__ rowbase, int col) {
    float4 v0 = src[4 * grp + 0], v1 = src[4 * grp + 1];
    float4 v2 = src[4 * grp + 2], v3 = src[4 * grp + 3];
    uint4 hi0, lo0, hi1, lo1;
    split8(v0, v1, hi0, lo0);
    split8(v2, v3, hi1, lo1);
    *(uint4*)(rowbase + col)             = hi0;
    *(uint4*)(rowbase + col + 8)         = hi1;
    *(uint4*)(rowbase + 1024 + col)      = lo0;
    *(uint4*)(rowbase + 1024 + col + 8)  = lo1;
}

__global__ void pack_all(const float4* __restrict__ x,
                         const float4* __restrict__ Wq,
                         const float4* __restrict__ Wk,
                         const float4* __restrict__ Wv,
                         const float* __restrict__ bq,
                         const float* __restrict__ bk,
                         const float* __restrict__ bv)
{
    const int b = blockIdx.x;
    const int tid = threadIdx.x;
    if (b < A_BLKS) {
        const int i = b * 256 + tid;        // 16-float group id
        const int e0  = i * 16;
        const int row = e0 >> 10;
        const int col = e0 & 1023;
        pack16(x, i, g_a16 + (size_t)row * 2048, col);
    } else if (b < A_BLKS + B_BLKS) {
        const int i = (b - A_BLKS) * 256 + tid;
        const int per = EDIM * EDIM / 16;   // 65536
        const int z = i / per;
        const int r = i - z * per;
        const float4* src = (z == 0 ? Wq : z == 1 ? Wk : Wv);
        const int e0  = r * 16;
        const int row = (e0 >> 10) + (z << 10);
        const int col = e0 & 1023;
        pack16(src, r, g_b16 + (size_t)row * 2048, col);
    } else {
        const int i = (b - A_BLKS - B_BLKS) * 256 + tid;
        if (i < NTOT) {
            const int z = i >> 10;
            g_bias[i] = (z == 0 ? bq : z == 1 ? bk : bv)[i & 1023];
        }
    }
}

// ---------------------------------------------------------------------------
// Persistent unified fp16 GEMM, seamless cp.async pipeline across tiles.
//   kt in [0,16):  Xh * Wh    [16,32): Xh * Wl    [32,48): Xl * Wh
// CTA 128x128, 256 thr (8 warps, 64x32 tiles), 3 stages, 2 CTAs/SM.
// KIT=48 % NSTG==0 -> slot rotation kt%3 is continuous across tiles, so the
// last two load slots of each tile prefetch the NEXT tile's stages 0/1.
// ---------------------------------------------------------------------------
#define GBM 128
#define GBN 128
#define GBK 64
#define NSTG 3
#define KIT 48
#define NTILE ((NTOT / GBN) * (M_TOK / GBM))   // 24*128 = 3072
#define A_STG 16384               // 128 rows * 128B
#define B_STG 16384
#define STG_BYTES (A_STG + B_STG) // 32768
#define SMEM_GEMM (NSTG * STG_BYTES + 128)

__device__ __forceinline__ u32 swz(int row, int c) {
    return (u32)(row * 128 + ((c ^ (row & 7)) << 4));
}

// per-thread tile base pointers from tile index (consecutive tiles share row-block)
__device__ __forceinline__ void tile_ptrs(int tile, int lr, int lc,
                                          const __half*& ap, const __half*& bp) {
    const int cblk = tile % (NTOT / GBN);
    const int rblk = tile / (NTOT / GBN);
    ap = g_a16 + (size_t)(rblk * GBM + lr) * 2048 + lc * 8;
    bp = g_b16 + (size_t)(cblk * GBN + lr) * 2048 + lc * 8;
}

__device__ __forceinline__ void load_stage(u32 aB, u32 bB, int it,
                                           const __half* aptr, const __half* bptr,
                                           u32 dA) {
    const int term = it >> 4;
    const int r16  = it & 15;
    const int ac = (term == 2) ? r16 + 16 : r16;   // A: lo only for term 2
    const int bc = (term == 1) ? r16 + 16 : r16;   // B: lo only for term 1
    const __half* as = aptr + ac * GBK;
    const __half* bs = bptr + bc * GBK;
    #pragma unroll
    for (int j = 0; j < 4; j++) {
        cpa16(aB + dA + j * (32 * 128), as + (size_t)j * 32 * 2048);
        cpa16(bB + dA + j * (32 * 128), bs + (size_t)j * 32 * 2048);
    }
}

__global__ void __launch_bounds__(256, 2)
qkv_mma_gemm()
{
    extern __shared__ char smraw[];
    const u32 smb = (s2u(smraw) + 127u) & ~127u;

    const int tid  = threadIdx.x;
    const int wid  = tid >> 5;
    const int lane = tid & 31;
    const int wm   = wid & 1;          // 0..1 -> 64 rows
    const int wn   = wid >> 1;         // 0..3 -> 32 cols
    const int lr   = tid >> 3;         // 0..31 (cp.async row within group)
    const int lc   = tid & 7;          // 16B chunk
    const u32 dA   = swz(lr, lc);

    int tile = blockIdx.x;
    const int stride = gridDim.x;

    const __half *ap, *bp;
    tile_ptrs(tile, lr, lc, ap, bp);

    // prologue: stages 0,1 of the first tile
    load_stage(smb, smb + A_STG, 0, ap, bp, dA); CPA_COMMIT();
    load_stage(smb + STG_BYTES, smb + STG_BYTES + A_STG, 1, ap, bp, dA); CPA_COMMIT();

    while (tile < NTILE) {
        const int ntile = tile + stride;
        const __half *nap = ap, *nbp = bp;
        if (ntile < NTILE) tile_ptrs(ntile, lr, lc, nap, nbp);

        float acc[4][4][4];
        #pragma unroll
        for (int i = 0; i < 4; i++)
            #pragma unroll
            for (int j = 0; j < 4; j++)
                #pragma unroll
                for (int k = 0; k < 4; k++) acc[i][j][k] = 0.f;

        #pragma unroll 3
        for (int kt = 0; kt < KIT; kt++) {
            const int slot = kt % NSTG;
            CPA_WAIT1();
            __syncthreads();

            // issue next stage: within-tile kt+2, or next tile's stage 0/1
            const int lit = kt + 2;
            const int ns = lit % NSTG;
            if (lit < KIT) {
                load_stage(smb + ns * STG_BYTES, smb + ns * STG_BYTES + A_STG,
                           lit, ap, bp, dA);
            } else if (ntile < NTILE) {
                load_stage(smb + ns * STG_BYTES, smb + ns * STG_BYTES + A_STG,
                           lit - KIT, nap, nbp, dA);
            }
            CPA_COMMIT();

            const u32 aB = smb + slot * STG_BYTES;
            const u32 bB = aB + A_STG;

            #pragma unroll
            for (int kk = 0; kk < 4; kk++) {
                u32 ra[4][4];
                #pragma unroll
                for (int mi = 0; mi < 4; mi++) {
                    const int r = wm * 64 + mi * 16 + (lane & 15);
                    const int c = kk * 2 + (lane >> 4);
                    ldsm4(ra[mi], aB + swz(r, c));
                }
                u32 rb[2][4];
                #pragma unroll
                for (int ni = 0; ni < 2; ni++) {
                    const int r = wn * 32 + ni * 16 + (lane & 7) + ((lane >> 4) << 3);
                    const int c = kk * 2 + ((lane >> 3) & 1);
                    ldsm4(rb[ni], bB + swz(r, c));
                }
                #pragma unroll
                for (int mi = 0; mi < 4; mi++)
                    #pragma unroll
                    for (int n8 = 0; n8 < 4; n8++)
                        mma_h32(acc[mi][n8], ra[mi], &rb[n8 >> 1][(n8 & 1) * 2]);
            }
        }

        // epilogue for this tile (next tile's stages 0/1 already in flight)
        {
            const int cblk = tile % (NTOT / GBN);
            const int rblk = tile / (NTOT / GBN);
            const int rbase = rblk * GBM + wm * 64;
            const int cbase = cblk * GBN + wn * 32;
            #pragma unroll
            for (int mi = 0; mi < 4; mi++) {
                const int r = rbase + mi * 16 + (lane >> 2);
                #pragma unroll
                for (int n8 = 0; n8 < 4; n8++) {
                    const int c = cbase + n8 * 8 + (lane & 3) * 2;
                    const float b0 = g_bias[c], b1 = g_bias[c + 1];
                    float2 v0 = make_float2(acc[mi][n8][0] + b0, acc[mi][n8][1] + b1);
                    float2 v1 = make_float2(acc[mi][n8][2] + b0, acc[mi][n8][3] + b1);
                    *(float2*)&g_qkv[(size_t)r * NTOT + c]       = v0;
                    *(float2*)&g_qkv[(size_t)(r + 8) * NTOT + c] = v1;
                }
            }
        }

        ap = nap; bp = nbp; tile = ntile;
    }
}

// ---------------------------------------------------------------------------
// Per-token head-head attention (R10 smem version, proven).
// 128 threads / 4 tokens per block; 32 threads per token = (head, D-half).
// Mask-before-softmax semantics.
// ---------------------------------------------------------------------------
__global__ __launch_bounds__(128)
void attn_kernel(const float* __restrict__ mask, float* __restrict__ out)
{
    __shared__ float ks[4 * HEADS * DH];
    __shared__ float vs[4 * HEADS * DH];
    __shared__ float ms[HEADS * HEADS];

    const int tid = threadIdx.x;
    const size_t tok0 = (size_t)blockIdx.x * 4;

    for (int i = tid; i < HEADS * HEADS; i += 128) ms[i] = mask[i];

    float4* ks4 = (float4*)ks;
    float4* vs4 = (float4*)vs;
    #pragma unroll
    for (int tt = 0; tt < 4; tt++) {
        const float4* kg = (const float4*)(g_qkv + (tok0 + tt) * NTOT + EDIM);
        const float4* vg = (const float4*)(g_qkv + (tok0 + tt) * NTOT + 2 * EDIM);
        #pragma unroll
        for (int j = 0; j < 2; j++) {
            const int idx = tid + j * 128;
            ks4[tt * 256 + idx] = kg[idx];
            vs4[tt * 256 + idx] = vg[idx];
        }
    }
    __syncthreads();

    const int t    = tid >> 5;
    const int lane = tid & 31;
    const int h    = lane & 15;
    const int half = lane >> 4;

    float4 qv[8];
    const float4* qp = (const float4*)(g_qkv + (tok0 + t) * NTOT + h * DH + half * 32);
    #pragma unroll
    for (int i = 0; i < 8; i++) qv[i] = qp[i];

    float s[16];
    #pragma unroll
    for (int g = 0; g < 16; g++) {
        const float4* kr = (const float4*)(ks + (t * HEADS + g) * DH + half * 32);
        float ax = 0.f, ay = 0.f, az = 0.f, aw = 0.f;
        #pragma unroll
        for (int i = 0; i < 8; i++) {
            float4 kv = kr[i];
            ax += qv[i].x * kv.x; ay += qv[i].y * kv.y;
            az += qv[i].z * kv.z; aw += qv[i].w * kv.w;
        }
        float p = (ax + ay) + (az + aw);
        p += __shfl_xor_sync(0xFFFFFFFFu, p, 16);
        s[g] = p * ms[h * HEADS + g];
    }

    float m = s[0];
    #pragma unroll
    for (int g = 1; g < 16; g++) m = fmaxf(m, s[g]);
    float denom = 0.f;
    #pragma unroll
    for (int g = 0; g < 16; g++) { s[g] = expf(s[g] - m); denom += s[g]; }
    const float inv = 1.f / denom;

    float4 o[8];
    #pragma unroll
    for (int i = 0; i < 8; i++) o[i] = make_float4(0.f, 0.f, 0.f, 0.f);
    #pragma unroll
    for (int g = 0; g < 16; g++) {
        const float p = s[g] * inv;
        const float4* vr = (const float4*)(vs + (t * HEADS + g) * DH + half * 32);
        #pragma unroll
        for (int i = 0; i < 8; i++) {
            float4 vv = vr[i];
            o[i].x += p * vv.x; o[i].y += p * vv.y;
            o[i].z += p * vv.z; o[i].w += p * vv.w;
        }
    }

    float4* op = (float4*)(out + (tok0 + t) * EDIM + h * DH + half * 32);
    #pragma unroll
    for (int i = 0; i < 8; i++) op[i] = o[i];
}

// ---------------------------------------------------------------------------
// Launch. Inputs: x, sparsity_pattern, Wq, bq, Wk, bk, Wv, bv
// ---------------------------------------------------------------------------
extern "C" void kernel_launch(void* const* d_in, const int* in_sizes, int n_in,
                              void* d_out, int out_size)
{
    (void)in_sizes; (void)n_in; (void)out_size;
    const float* x  = (const float*)d_in[0];
    const float* sp = (const float*)d_in[1];
    const float* Wq = (const float*)d_in[2];
    const float* bq = (const float*)d_in[3];
    const float* Wk = (const float*)d_in[4];
    const float* bk = (const float*)d_in[5];
    const float* Wv = (const float*)d_in[6];
    const float* bv = (const float*)d_in[7];
    float* out = (float*)d_out;

    pack_all<<<A_BLKS + B_BLKS + BIAS_BLKS, 256>>>(
        (const float4*)x, (const float4*)Wq, (const float4*)Wk,
        (const float4*)Wv, bq, bk, bv);

    int nsm = 148;
    cudaDeviceGetAttribute(&nsm, cudaDevAttrMultiProcessorCount, 0);
    cudaFuncSetAttribute(qkv_mma_gemm,
                         cudaFuncAttributeMaxDynamicSharedMemorySize, SMEM_GEMM);
    qkv_mma_gemm<<<2 * nsm, 256, SMEM_GEMM>>>();

    attn_kernel<<<M_TOK / 4, 128>>>(sp, out);
}

// round 16
// speedup vs baseline: 1.0365x; 1.0365x over previous
#include <cuda_runtime.h>
#include <cuda_fp16.h>
#include <cstdint>

// Problem constants
#define BATCH  4
#define SEQ    4096
#define M_TOK  (BATCH * SEQ)   // 16384 tokens
#define EDIM   1024
#define HEADS  16
#define DH     64
#define NTOT   3072            // packed N = q|k|v

typedef unsigned long long u64;
typedef unsigned int       u32;

// ---------------------------------------------------------------------------
// Device scratch (alloc-free per harness rules)
// A rows: [Xh(1024) | Xl(1024)]  fp16, residual UNSCALED (denormals OK on TC)
// B rows: [Wh(1024) | Wl(1024)]
// Terms: (hi,hi) + (hi,lo) + (lo,hi), all into one f32 accumulator.
// ---------------------------------------------------------------------------
__device__ __half g_a16[(size_t)M_TOK * 2048];
__device__ __half g_b16[(size_t)NTOT * 2048];
__device__ float  g_bias[NTOT];
__device__ float  g_qkv[(size_t)M_TOK * NTOT];   // q | k | v per row

// ---------------------------------------------------------------------------
// PTX helpers (compute_103-legal: cp.async / ldmatrix / mma.sync)
// ---------------------------------------------------------------------------
__device__ __forceinline__ u32 s2u(const void* p) {
    u32 a;
    asm("{ .reg .u64 t; cvta.to.shared.u64 t, %1; cvt.u32.u64 %0, t; }"
        : "=r"(a) : "l"(p));
    return a;
}
__device__ __forceinline__ void cpa16(u32 dst, const void* src) {
    asm volatile("cp.async.cg.shared.global [%0], [%1], 16;"
                 :: "r"(dst), "l"(src) : "memory");
}
#define CPA_COMMIT() asm volatile("cp.async.commit_group;" ::: "memory")
#define CPA_WAIT1()  asm volatile("cp.async.wait_group 1;" ::: "memory")

__device__ __forceinline__ void ldsm4(u32* r, u32 addr) {
    asm volatile("ldmatrix.sync.aligned.m8n8.x4.shared.b16 {%0,%1,%2,%3}, [%4];"
                 : "=r"(r[0]), "=r"(r[1]), "=r"(r[2]), "=r"(r[3]) : "r"(addr));
}
__device__ __forceinline__ void mma_h32(float* d, const u32* a, const u32* b) {
    asm volatile(
        "mma.sync.aligned.m16n8k16.row.col.f32.f16.f16.f32 "
        "{%0,%1,%2,%3}, {%4,%5,%6,%7}, {%8,%9}, {%0,%1,%2,%3};"
        : "+f"(d[0]), "+f"(d[1]), "+f"(d[2]), "+f"(d[3])
        : "r"(a[0]), "r"(a[1]), "r"(a[2]), "r"(a[3]), "r"(b[0]), "r"(b[1]));
}

// ---------------------------------------------------------------------------
// Fused pack kernel: A split, B split, bias — one launch (R15, proven 27us).
// 16 floats per thread for A/B (4 float4 loads, 4 uint4 stores).
// ---------------------------------------------------------------------------
#define A_BLKS 4096   // (M_TOK*EDIM/16)/256
#define B_BLKS 768    // (3*EDIM*EDIM/16)/256
#define BIAS_BLKS 12

__device__ __forceinline__ void split8(float4 v0, float4 v1, uint4& hi, uint4& lo) {
    float f[8] = {v0.x, v0.y, v0.z, v0.w, v1.x, v1.y, v1.z, v1.w};
    u32 hw[4], lw[4];
    #pragma unroll
    for (int j = 0; j < 4; j++) {
        __half ha = __float2half_rn(f[2 * j]);
        __half hb = __float2half_rn(f[2 * j + 1]);
        __half2 hh = __halves2half2(ha, hb);
        __half2 ll = __halves2half2(
            __float2half_rn(f[2 * j]     - __half2float(ha)),
            __float2half_rn(f[2 * j + 1] - __half2float(hb)));
        hw[j] = *(u32*)&hh;
        lw[j] = *(u32*)&ll;
    }
    hi = make_uint4(hw[0], hw[1], hw[2], hw[3]);
    lo = make_uint4(lw[0], lw[1], lw[2], lw[3]);
}

__device__ __forceinline__ void pack16(const float4* __restrict__ src, int grp,
                                       __half* __restrict__ rowbase, int col) {
    float4 v0 = src[4 * grp + 0], v1 = src[4 * grp + 1];
    float4 v2 = src[4 * grp + 2], v3 = src[4 * grp + 3];
    uint4 hi0, lo0, hi1, lo1;
    split8(v0, v1, hi0, lo0);
    split8(v2, v3, hi1, lo1);
    *(uint4*)(rowbase + col)             = hi0;
    *(uint4*)(rowbase + col + 8)         = hi1;
    *(uint4*)(rowbase + 1024 + col)      = lo0;
    *(uint4*)(rowbase + 1024 + col + 8)  = lo1;
}

__global__ void pack_all(const float4* __restrict__ x,
                         const float4* __restrict__ Wq,
                         const float4* __restrict__ Wk,
                         const float4* __restrict__ Wv,
                         const float* __restrict__ bq,
                         const float* __restrict__ bk,
                         const float* __restrict__ bv)
{
    const int b = blockIdx.x;
    const int tid = threadIdx.x;
    if (b < A_BLKS) {
        const int i = b * 256 + tid;        // 16-float group id
        const int e0  = i * 16;
        const int row = e0 >> 10;
        const int col = e0 & 1023;
        pack16(x, i, g_a16 + (size_t)row * 2048, col);
    } else if (b < A_BLKS + B_BLKS) {
        const int i = (b - A_BLKS) * 256 + tid;
        const int per = EDIM * EDIM / 16;   // 65536
        const int z = i / per;
        const int r = i - z * per;
        const float4* src = (z == 0 ? Wq : z == 1 ? Wk : Wv);
        const int e0  = r * 16;
        const int row = (e0 >> 10) + (z << 10);
        const int col = e0 & 1023;
        pack16(src, r, g_b16 + (size_t)row * 2048, col);
    } else {
        const int i = (b - A_BLKS - B_BLKS) * 256 + tid;
        if (i < NTOT) {
            const int z = i >> 10;
            g_bias[i] = (z == 0 ? bq : z == 1 ? bk : bv)[i & 1023];
        }
    }
}

// ---------------------------------------------------------------------------
// Unified fp16 GEMM, 48 iterations over one f32 accumulator (R10/R14, proven):
//   kt in [0,16):  Xh * Wh      kt in [16,32): Xh * Wl      kt in [32,48): Xl * Wh
// CTA 128x128, 256 thr (8 warps, 64x32 tiles), 3-stage cp.async, 2 CTAs/SM.
// Grid-scheduled (HW dynamic balancing beats static persistent assignment).
// ---------------------------------------------------------------------------
#define GBM 128
#define GBN 128
#define GBK 64
#define NSTG 3
#define KIT 48
#define A_STG 16384               // 128 rows * 128B
#define B_STG 16384
#define STG_BYTES (A_STG + B_STG) // 32768
#define SMEM_GEMM (NSTG * STG_BYTES + 128)

__device__ __forceinline__ u32 swz(int row, int c) {
    return (u32)(row * 128 + ((c ^ (row & 7)) << 4));
}

// aptr/bptr: per-thread global base (row tid>>3, chunk tid&7 pre-applied).
__device__ __forceinline__ void load_stage(u32 aB, u32 bB, int it,
                                           const __half* aptr, const __half* bptr,
                                           u32 dA, u32 dB) {
    const int term = it >> 4;
    const int r16  = it & 15;
    const int ac = (term == 2) ? r16 + 16 : r16;   // A: lo only for term 2
    const int bc = (term == 1) ? r16 + 16 : r16;   // B: lo only for term 1
    const __half* as = aptr + ac * GBK;
    const __half* bs = bptr + bc * GBK;
    #pragma unroll
    for (int j = 0; j < 4; j++) {
        cpa16(aB + dA + j * (32 * 128), as + (size_t)j * 32 * 2048);
        cpa16(bB + dB + j * (32 * 128), bs + (size_t)j * 32 * 2048);
    }
}

__global__ void __launch_bounds__(256, 2)
qkv_mma_gemm()
{
    extern __shared__ char smraw[];
    const u32 smb = (s2u(smraw) + 127u) & ~127u;

    const int tid  = threadIdx.x;
    const int wid  = tid >> 5;
    const int lane = tid & 31;
    const int wm   = wid & 1;          // 0..1 -> 64 rows
    const int wn   = wid >> 1;         // 0..3 -> 32 cols
    const int row0 = blockIdx.y * GBM;
    const int col0 = blockIdx.x * GBN;

    // per-thread cp.async source bases and swizzled dst offsets
    const int lr = tid >> 3;           // 0..31 (row within 32-row group)
    const int lc = tid & 7;            // 16B chunk
    const __half* aptr = g_a16 + (size_t)(row0 + lr) * 2048 + lc * 8;
    const __half* bptr = g_b16 + (size_t)(col0 + lr) * 2048 + lc * 8;
    const u32 dA = swz(lr, lc);
    const u32 dB = swz(lr, lc);

    float acc[4][4][4];
    #pragma unroll
    for (int i = 0; i < 4; i++)
        #pragma unroll
        for (int j = 0; j < 4; j++)
            #pragma unroll
            for (int k = 0; k < 4; k++) acc[i][j][k] = 0.f;

    // prologue: stages 0,1
    load_stage(smb, smb + A_STG, 0, aptr, bptr, dA, dB); CPA_COMMIT();
    load_stage(smb + STG_BYTES, smb + STG_BYTES + A_STG, 1, aptr, bptr, dA, dB); CPA_COMMIT();

    #pragma unroll 3
    for (int kt = 0; kt < KIT; kt++) {
        const int slot = kt % NSTG;
        CPA_WAIT1();
        __syncthreads();

        // issue next stage immediately (that slot was last read pre-barrier)
        if (kt + 2 < KIT) {
            const int ns = (kt + 2) % NSTG;
            load_stage(smb + ns * STG_BYTES, smb + ns * STG_BYTES + A_STG,
                       kt + 2, aptr, bptr, dA, dB);
        }
        CPA_COMMIT();

        const u32 aB = smb + slot * STG_BYTES;
        const u32 bB = aB + A_STG;

        #pragma unroll
        for (int kk = 0; kk < 4; kk++) {
            u32 ra[4][4];
            #pragma unroll
            for (int mi = 0; mi < 4; mi++) {
                const int r = wm * 64 + mi * 16 + (lane & 15);
                const int c = kk * 2 + (lane >> 4);
                ldsm4(ra[mi], aB + swz(r, c));
            }
            u32 rb[2][4];
            #pragma unroll
            for (int ni = 0; ni < 2; ni++) {
                const int r = wn * 32 + ni * 16 + (lane & 7) + ((lane >> 4) << 3);
                const int c = kk * 2 + ((lane >> 3) & 1);
                ldsm4(rb[ni], bB + swz(r, c));
            }
            #pragma unroll
            for (int mi = 0; mi < 4; mi++)
                #pragma unroll
                for (int n8 = 0; n8 < 4; n8++)
                    mma_h32(acc[mi][n8], ra[mi], &rb[n8 >> 1][(n8 & 1) * 2]);
        }
    }

    // epilogue: add bias, write g_qkv
    const int rbase = row0 + wm * 64;
    const int cbase = col0 + wn * 32;
    #pragma unroll
    for (int mi = 0; mi < 4; mi++) {
        const int r = rbase + mi * 16 + (lane >> 2);
        #pragma unroll
        for (int n8 = 0; n8 < 4; n8++) {
            const int c = cbase + n8 * 8 + (lane & 3) * 2;
            const float b0 = g_bias[c], b1 = g_bias[c + 1];
            float2 v0 = make_float2(acc[mi][n8][0] + b0, acc[mi][n8][1] + b1);
            float2 v1 = make_float2(acc[mi][n8][2] + b0, acc[mi][n8][3] + b1);
            *(float2*)&g_qkv[(size_t)r * NTOT + c]       = v0;
            *(float2*)&g_qkv[(size_t)(r + 8) * NTOT + c] = v1;
        }
    }
}

// ---------------------------------------------------------------------------
// Per-token head-head attention (R10 smem version, proven).
// 128 threads / 4 tokens per block; 32 threads per token = (head, D-half).
// Mask-before-softmax semantics.
// ---------------------------------------------------------------------------
__global__ __launch_bounds__(128)
void attn_kernel(const float* __restrict__ mask, float* __restrict__ out)
{
    __shared__ float ks[4 * HEADS * DH];
    __shared__ float vs[4 * HEADS * DH];
    __shared__ float ms[HEADS * HEADS];

    const int tid = threadIdx.x;
    const size_t tok0 = (size_t)blockIdx.x * 4;

    for (int i = tid; i < HEADS * HEADS; i += 128) ms[i] = mask[i];

    float4* ks4 = (float4*)ks;
    float4* vs4 = (float4*)vs;
    #pragma unroll
    for (int tt = 0; tt < 4; tt++) {
        const float4* kg = (const float4*)(g_qkv + (tok0 + tt) * NTOT + EDIM);
        const float4* vg = (const float4*)(g_qkv + (tok0 + tt) * NTOT + 2 * EDIM);
        #pragma unroll
        for (int j = 0; j < 2; j++) {
            const int idx = tid + j * 128;
            ks4[tt * 256 + idx] = kg[idx];
            vs4[tt * 256 + idx] = vg[idx];
        }
    }
    __syncthreads();

    const int t    = tid >> 5;
    const int lane = tid & 31;
    const int h    = lane & 15;
    const int half = lane >> 4;

    float4 qv[8];
    const float4* qp = (const float4*)(g_qkv + (tok0 + t) * NTOT + h * DH + half * 32);
    #pragma unroll
    for (int i = 0; i < 8; i++) qv[i] = qp[i];

    float s[16];
    #pragma unroll
    for (int g = 0; g < 16; g++) {
        const float4* kr = (const float4*)(ks + (t * HEADS + g) * DH + half * 32);
        float ax = 0.f, ay = 0.f, az = 0.f, aw = 0.f;
        #pragma unroll
        for (int i = 0; i < 8; i++) {
            float4 kv = kr[i];
            ax += qv[i].x * kv.x; ay += qv[i].y * kv.y;
            az += qv[i].z * kv.z; aw += qv[i].w * kv.w;
        }
        float p = (ax + ay) + (az + aw);
        p += __shfl_xor_sync(0xFFFFFFFFu, p, 16);
        s[g] = p * ms[h * HEADS + g];
    }

    float m = s[0];
    #pragma unroll
    for (int g = 1; g < 16; g++) m = fmaxf(m, s[g]);
    float denom = 0.f;
    #pragma unroll
    for (int g = 0; g < 16; g++) { s[g] = expf(s[g] - m); denom += s[g]; }
    const float inv = 1.f / denom;

    float4 o[8];
    #pragma unroll
    for (int i = 0; i < 8; i++) o[i] = make_float4(0.f, 0.f, 0.f, 0.f);
    #pragma unroll
    for (int g = 0; g < 16; g++) {
        const float p = s[g] * inv;
        const float4* vr = (const float4*)(vs + (t * HEADS + g) * DH + half * 32);
        #pragma unroll
        for (int i = 0; i < 8; i++) {
            float4 vv = vr[i];
            o[i].x += p * vv.x; o[i].y += p * vv.y;
            o[i].z += p * vv.z; o[i].w += p * vv.w;
        }
    }

    float4* op = (float4*)(out + (tok0 + t) * EDIM + h * DH + half * 32);
    #pragma unroll
    for (int i = 0; i < 8; i++) op[i] = o[i];
}

// ---------------------------------------------------------------------------
// Launch. Inputs: x, sparsity_pattern, Wq, bq, Wk, bk, Wv, bv
// ---------------------------------------------------------------------------
extern "C" void kernel_launch(void* const* d_in, const int* in_sizes, int n_in,
                              void* d_out, int out_size)
{
    (void)in_sizes; (void)n_in; (void)out_size;
    const float* x  = (const float*)d_in[0];
    const float* sp = (const float*)d_in[1];
    const float* Wq = (const float*)d_in[2];
    const float* bq = (const float*)d_in[3];
    const float* Wk = (const float*)d_in[4];
    const float* bk = (const float*)d_in[5];
    const float* Wv = (const float*)d_in[6];
    const float* bv = (const float*)d_in[7];
    float* out = (float*)d_out;

    pack_all<<<A_BLKS + B_BLKS + BIAS_BLKS, 256>>>(
        (const float4*)x, (const float4*)Wq, (const float4*)Wk,
        (const float4*)Wv, bq, bk, bv);

    cudaFuncSetAttribute(qkv_mma_gemm,
                         cudaFuncAttributeMaxDynamicSharedMemorySize, SMEM_GEMM);
    dim3 grid(NTOT / GBN, M_TOK / GBM);    // (24, 128)
    qkv_mma_gemm<<<grid, 256, SMEM_GEMM>>>();

    attn_kernel<<<M_TOK / 4, 128>>>(sp, out);
}

// round 17
// speedup vs baseline: 1.0482x; 1.0112x over previous
#include <cuda_runtime.h>
#include <cuda_fp16.h>
#include <cstdint>

// Problem constants
#define BATCH  4
#define SEQ    4096
#define M_TOK  (BATCH * SEQ)   // 16384 tokens
#define EDIM   1024
#define HEADS  16
#define DH     64
#define NTOT   3072            // packed N = q|k|v

typedef unsigned long long u64;
typedef unsigned int       u32;

// ---------------------------------------------------------------------------
// Device scratch (alloc-free per harness rules)
// ---------------------------------------------------------------------------
__device__ __half g_a16[(size_t)M_TOK * 2048];   // [Xh | Xl] per row
__device__ __half g_b16[(size_t)NTOT * 2048];    // [Wh | Wl] per row
__device__ float  g_bias[NTOT];
__device__ float  g_qkv[(size_t)M_TOK * NTOT];   // q | k | v per row

// ---------------------------------------------------------------------------
// PTX helpers (compute_103-legal: cp.async / ldmatrix / mma.sync)
// ---------------------------------------------------------------------------
__device__ __forceinline__ u32 s2u(const void* p) {
    u32 a;
    asm("{ .reg .u64 t; cvta.to.shared.u64 t, %1; cvt.u32.u64 %0, t; }"
        : "=r"(a) : "l"(p));
    return a;
}
__device__ __forceinline__ void cpa16(u32 dst, const void* src) {
    asm volatile("cp.async.cg.shared.global [%0], [%1], 16;"
                 :: "r"(dst), "l"(src) : "memory");
}
#define CPA_COMMIT() asm volatile("cp.async.commit_group;" ::: "memory")
#define CPA_WAIT1()  asm volatile("cp.async.wait_group 1;" ::: "memory")
#define CPA_WAIT0()  asm volatile("cp.async.wait_group 0;" ::: "memory")

__device__ __forceinline__ void ldsm4(u32* r, u32 addr) {
    asm volatile("ldmatrix.sync.aligned.m8n8.x4.shared.b16 {%0,%1,%2,%3}, [%4];"
                 : "=r"(r[0]), "=r"(r[1]), "=r"(r[2]), "=r"(r[3]) : "r"(addr));
}
__device__ __forceinline__ void mma_h32(float* d, const u32* a, const u32* b) {
    asm volatile(
        "mma.sync.aligned.m16n8k16.row.col.f32.f16.f16.f32 "
        "{%0,%1,%2,%3}, {%4,%5,%6,%7}, {%8,%9}, {%0,%1,%2,%3};"
        : "+f"(d[0]), "+f"(d[1]), "+f"(d[2]), "+f"(d[3])
        : "r"(a[0]), "r"(a[1]), "r"(a[2]), "r"(a[3]), "r"(b[0]), "r"(b[1]));
}

// ---------------------------------------------------------------------------
// Fused pack kernel (R15/R16, proven 27us).
// ---------------------------------------------------------------------------
#define A_BLKS 4096   // (M_TOK*EDIM/16)/256
#define B_BLKS 768    // (3*EDIM*EDIM/16)/256
#define BIAS_BLKS 12

__device__ __forceinline__ void split8(float4 v0, float4 v1, uint4& hi, uint4& lo) {
    float f[8] = {v0.x, v0.y, v0.z, v0.w, v1.x, v1.y, v1.z, v1.w};
    u32 hw[4], lw[4];
    #pragma unroll
    for (int j = 0; j < 4; j++) {
        __half ha = __float2half_rn(f[2 * j]);
        __half hb = __float2half_rn(f[2 * j + 1]);
        __half2 hh = __halves2half2(ha, hb);
        __half2 ll = __halves2half2(
            __float2half_rn(f[2 * j]     - __half2float(ha)),
            __float2half_rn(f[2 * j + 1] - __half2float(hb)));
        hw[j] = *(u32*)&hh;
        lw[j] = *(u32*)&ll;
    }
    hi = make_uint4(hw[0], hw[1], hw[2], hw[3]);
    lo = make_uint4(lw[0], lw[1], lw[2], lw[3]);
}

__device__ __forceinline__ void pack16(const float4* __restrict__ src, int grp,
                                       __half* __restrict__ rowbase, int col) {
    float4 v0 = src[4 * grp + 0], v1 = src[4 * grp + 1];
    float4 v2 = src[4 * grp + 2], v3 = src[4 * grp + 3];
    uint4 hi0, lo0, hi1, lo1;
    split8(v0, v1, hi0, lo0);
    split8(v2, v3, hi1, lo1);
    *(uint4*)(rowbase + col)             = hi0;
    *(uint4*)(rowbase + col + 8)         = hi1;
    *(uint4*)(rowbase + 1024 + col)      = lo0;
    *(uint4*)(rowbase + 1024 + col + 8)  = lo1;
}

__global__ void pack_all(const float4* __restrict__ x,
                         const float4* __restrict__ Wq,
                         const float4* __restrict__ Wk,
                         const float4* __restrict__ Wv,
                         const float* __restrict__ bq,
                         const float* __restrict__ bk,
                         const float* __restrict__ bv)
{
    const int b = blockIdx.x;
    const int tid = threadIdx.x;
    if (b < A_BLKS) {
        const int i = b * 256 + tid;
        const int e0  = i * 16;
        const int row = e0 >> 10;
        const int col = e0 & 1023;
        pack16(x, i, g_a16 + (size_t)row * 2048, col);
    } else if (b < A_BLKS + B_BLKS) {
        const int i = (b - A_BLKS) * 256 + tid;
        const int per = EDIM * EDIM / 16;
        const int z = i / per;
        const int r = i - z * per;
        const float4* src = (z == 0 ? Wq : z == 1 ? Wk : Wv);
        const int e0  = r * 16;
        const int row = (e0 >> 10) + (z << 10);
        const int col = e0 & 1023;
        pack16(src, r, g_b16 + (size_t)row * 2048, col);
    } else {
        const int i = (b - A_BLKS - B_BLKS) * 256 + tid;
        if (i < NTOT) {
            const int z = i >> 10;
            g_bias[i] = (z == 0 ? bq : z == 1 ? bk : bv)[i & 1023];
        }
    }
}

// ---------------------------------------------------------------------------
// Unified fp16 GEMM (R10/R14/R16, proven 664us). Unchanged.
// ---------------------------------------------------------------------------
#define GBM 128
#define GBN 128
#define GBK 64
#define NSTG 3
#define KIT 48
#define A_STG 16384
#define B_STG 16384
#define STG_BYTES (A_STG + B_STG)
#define SMEM_GEMM (NSTG * STG_BYTES + 128)

__device__ __forceinline__ u32 swz(int row, int c) {
    return (u32)(row * 128 + ((c ^ (row & 7)) << 4));
}

__device__ __forceinline__ void load_stage(u32 aB, u32 bB, int it,
                                           const __half* aptr, const __half* bptr,
                                           u32 dA, u32 dB) {
    const int term = it >> 4;
    const int r16  = it & 15;
    const int ac = (term == 2) ? r16 + 16 : r16;
    const int bc = (term == 1) ? r16 + 16 : r16;
    const __half* as = aptr + ac * GBK;
    const __half* bs = bptr + bc * GBK;
    #pragma unroll
    for (int j = 0; j < 4; j++) {
        cpa16(aB + dA + j * (32 * 128), as + (size_t)j * 32 * 2048);
        cpa16(bB + dB + j * (32 * 128), bs + (size_t)j * 32 * 2048);
    }
}

__global__ void __launch_bounds__(256, 2)
qkv_mma_gemm()
{
    extern __shared__ char smraw[];
    const u32 smb = (s2u(smraw) + 127u) & ~127u;

    const int tid  = threadIdx.x;
    const int wid  = tid >> 5;
    const int lane = tid & 31;
    const int wm   = wid & 1;
    const int wn   = wid >> 1;
    const int row0 = blockIdx.y * GBM;
    const int col0 = blockIdx.x * GBN;

    const int lr = tid >> 3;
    const int lc = tid & 7;
    const __half* aptr = g_a16 + (size_t)(row0 + lr) * 2048 + lc * 8;
    const __half* bptr = g_b16 + (size_t)(col0 + lr) * 2048 + lc * 8;
    const u32 dA = swz(lr, lc);
    const u32 dB = swz(lr, lc);

    float acc[4][4][4];
    #pragma unroll
    for (int i = 0; i < 4; i++)
        #pragma unroll
        for (int j = 0; j < 4; j++)
            #pragma unroll
            for (int k = 0; k < 4; k++) acc[i][j][k] = 0.f;

    load_stage(smb, smb + A_STG, 0, aptr, bptr, dA, dB); CPA_COMMIT();
    load_stage(smb + STG_BYTES, smb + STG_BYTES + A_STG, 1, aptr, bptr, dA, dB); CPA_COMMIT();

    #pragma unroll 3
    for (int kt = 0; kt < KIT; kt++) {
        const int slot = kt % NSTG;
        CPA_WAIT1();
        __syncthreads();

        if (kt + 2 < KIT) {
            const int ns = (kt + 2) % NSTG;
            load_stage(smb + ns * STG_BYTES, smb + ns * STG_BYTES + A_STG,
                       kt + 2, aptr, bptr, dA, dB);
        }
        CPA_COMMIT();

        const u32 aB = smb + slot * STG_BYTES;
        const u32 bB = aB + A_STG;

        #pragma unroll
        for (int kk = 0; kk < 4; kk++) {
            u32 ra[4][4];
            #pragma unroll
            for (int mi = 0; mi < 4; mi++) {
                const int r = wm * 64 + mi * 16 + (lane & 15);
                const int c = kk * 2 + (lane >> 4);
                ldsm4(ra[mi], aB + swz(r, c));
            }
            u32 rb[2][4];
            #pragma unroll
            for (int ni = 0; ni < 2; ni++) {
                const int r = wn * 32 + ni * 16 + (lane & 7) + ((lane >> 4) << 3);
                const int c = kk * 2 + ((lane >> 3) & 1);
                ldsm4(rb[ni], bB + swz(r, c));
            }
            #pragma unroll
            for (int mi = 0; mi < 4; mi++)
                #pragma unroll
                for (int n8 = 0; n8 < 4; n8++)
                    mma_h32(acc[mi][n8], ra[mi], &rb[n8 >> 1][(n8 & 1) * 2]);
        }
    }

    const int rbase = row0 + wm * 64;
    const int cbase = col0 + wn * 32;
    #pragma unroll
    for (int mi = 0; mi < 4; mi++) {
        const int r = rbase + mi * 16 + (lane >> 2);
        #pragma unroll
        for (int n8 = 0; n8 < 4; n8++) {
            const int c = cbase + n8 * 8 + (lane & 3) * 2;
            const float b0 = g_bias[c], b1 = g_bias[c + 1];
            float2 v0 = make_float2(acc[mi][n8][0] + b0, acc[mi][n8][1] + b1);
            float2 v1 = make_float2(acc[mi][n8][2] + b0, acc[mi][n8][3] + b1);
            *(float2*)&g_qkv[(size_t)r * NTOT + c]       = v0;
            *(float2*)&g_qkv[(size_t)(r + 8) * NTOT + c] = v1;
        }
    }
}

// ---------------------------------------------------------------------------
// Per-token head-head attention, MUFU-deduped + cp.async overlapped.
// 128 threads / 4 tokens per block; thread = (token, head, D-half).
// Each thread exps only its half's 8 scores; partner p's come via shfl.
// k staged in cp.async group 0, v in group 1 (v flies during softmax).
// Mask-before-softmax semantics preserved.
// ---------------------------------------------------------------------------
__global__ __launch_bounds__(128)
void attn_kernel(const float* __restrict__ mask, float* __restrict__ out)
{
    __shared__ float ks[4 * HEADS * DH];   // 16 KB
    __shared__ float vs[4 * HEADS * DH];   // 16 KB
    __shared__ float ms[HEADS * HEADS];    // 1 KB

    const int tid = threadIdx.x;
    const size_t tok0 = (size_t)blockIdx.x * 4;

    for (int i = tid; i < HEADS * HEADS; i += 128) ms[i] = mask[i];

    const u32 ksa = s2u(ks);
    const u32 vsa = s2u(vs);

    // stage k (group A), then v (group B), via cp.async
    #pragma unroll
    for (int tt = 0; tt < 4; tt++) {
        const float* kg = g_qkv + (tok0 + tt) * NTOT + EDIM;
        #pragma unroll
        for (int j = 0; j < 2; j++) {
            const int idx = tid + j * 128;               // float4 index 0..255
            cpa16(ksa + (tt * 256 + idx) * 16, kg + idx * 4);
        }
    }
    CPA_COMMIT();
    #pragma unroll
    for (int tt = 0; tt < 4; tt++) {
        const float* vg = g_qkv + (tok0 + tt) * NTOT + 2 * EDIM;
        #pragma unroll
        for (int j = 0; j < 2; j++) {
            const int idx = tid + j * 128;
            cpa16(vsa + (tt * 256 + idx) * 16, vg + idx * 4);
        }
    }
    CPA_COMMIT();

    const int t    = tid >> 5;       // token (one warp per token)
    const int lane = tid & 31;
    const int h    = lane & 15;      // head
    const int half = lane >> 4;      // D-half

    // q half-row into registers (overlaps with k/v staging)
    float4 qv[8];
    const float4* qp = (const float4*)(g_qkv + (tok0 + t) * NTOT + h * DH + half * 32);
    #pragma unroll
    for (int i = 0; i < 8; i++) qv[i] = qp[i];

    CPA_WAIT1();        // k staged (v may still be in flight)
    __syncthreads();

    // scores: partial dot over this half, combine with partner via shfl
    float s[16];
    #pragma unroll
    for (int g = 0; g < 16; g++) {
        const float4* kr = (const float4*)(ks + (t * HEADS + g) * DH + half * 32);
        float ax = 0.f, ay = 0.f, az = 0.f, aw = 0.f;
        #pragma unroll
        for (int i = 0; i < 8; i++) {
            float4 kv = kr[i];
            ax += qv[i].x * kv.x; ay += qv[i].y * kv.y;
            az += qv[i].z * kv.z; aw += qv[i].w * kv.w;
        }
        float p = (ax + ay) + (az + aw);
        p += __shfl_xor_sync(0xFFFFFFFFu, p, 16);
        s[g] = p * ms[h * HEADS + g];
    }

    // softmax, exp-deduplicated: this thread exps g in [half*8, half*8+8)
    float m = s[0];
    #pragma unroll
    for (int g = 1; g < 16; g++) m = fmaxf(m, s[g]);

    float e[8];
    float dsum = 0.f;
    #pragma unroll
    for (int j = 0; j < 8; j++) {
        e[j] = __expf(s[half * 8 + j] - m);
        dsum += e[j];
    }
    dsum += __shfl_xor_sync(0xFFFFFFFFu, dsum, 16);
    const float inv = 1.f / dsum;

    float own[8], oth[8];
    #pragma unroll
    for (int j = 0; j < 8; j++) {
        own[j] = e[j] * inv;
        oth[j] = __shfl_xor_sync(0xFFFFFFFFu, own[j], 16);
    }

    CPA_WAIT0();        // v staged
    __syncthreads();

    // out half-row = sum_g p_g * v[g][half]; own g = half*8+j, partner g = (1-half)*8+j
    float4 o[8];
    #pragma unroll
    for (int i = 0; i < 8; i++) o[i] = make_float4(0.f, 0.f, 0.f, 0.f);

    const int gown = half * 8;
    const int goth = (1 - half) * 8;
    #pragma unroll
    for (int j = 0; j < 8; j++) {
        const float p = own[j];
        const float4* vr = (const float4*)(vs + (t * HEADS + gown + j) * DH + half * 32);
        #pragma unroll
        for (int i = 0; i < 8; i++) {
            float4 vv = vr[i];
            o[i].x += p * vv.x; o[i].y += p * vv.y;
            o[i].z += p * vv.z; o[i].w += p * vv.w;
        }
    }
    #pragma unroll
    for (int j = 0; j < 8; j++) {
        const float p = oth[j];
        const float4* vr = (const float4*)(vs + (t * HEADS + goth + j) * DH + half * 32);
        #pragma unroll
        for (int i = 0; i < 8; i++) {
            float4 vv = vr[i];
            o[i].x += p * vv.x; o[i].y += p * vv.y;
            o[i].z += p * vv.z; o[i].w += p * vv.w;
        }
    }

    float4* op = (float4*)(out + (tok0 + t) * EDIM + h * DH + half * 32);
    #pragma unroll
    for (int i = 0; i < 8; i++) op[i] = o[i];
}

// ---------------------------------------------------------------------------
// Launch. Inputs: x, sparsity_pattern, Wq, bq, Wk, bk, Wv, bv
// ---------------------------------------------------------------------------
extern "C" void kernel_launch(void* const* d_in, const int* in_sizes, int n_in,
                              void* d_out, int out_size)
{
    (void)in_sizes; (void)n_in; (void)out_size;
    const float* x  = (const float*)d_in[0];
    const float* sp = (const float*)d_in[1];
    const float* Wq = (const float*)d_in[2];
    const float* bq = (const float*)d_in[3];
    const float* Wk = (const float*)d_in[4];
    const float* bk = (const float*)d_in[5];
    const float* Wv = (const float*)d_in[6];
    const float* bv = (const float*)d_in[7];
    float* out = (float*)d_out;

    pack_all<<<A_BLKS + B_BLKS + BIAS_BLKS, 256>>>(
        (const float4*)x, (const float4*)Wq, (const float4*)Wk,
        (const float4*)Wv, bq, bk, bv);

    cudaFuncSetAttribute(qkv_mma_gemm,
                         cudaFuncAttributeMaxDynamicSharedMemorySize, SMEM_GEMM);
    dim3 grid(NTOT / GBN, M_TOK / GBM);    // (24, 128)
    qkv_mma_gemm<<<grid, 256, SMEM_GEMM>>>();

    attn_kernel<<<M_TOK / 4, 128>>>(sp, out);
}